// round 2
// baseline (speedup 1.0000x reference)
#include <cuda_runtime.h>

// MMD loss in closed form over column statistics:
//   result = 7.75 * n(n-1) * ||colsum(s)-colsum(t)||^2
//            / ((n*(sum s^2 + sum t^2) - ||colsum(s)+colsum(t)||^2) * B^2),  n = 2B
// The (max-min) scale factor cancels exactly. Single fused kernel:
// all blocks stream partials, the last-arriving block finalizes.

#define NBLK 148
#define NTHR 512
#define DDIM 256
#define D4   64   // DDIM / 4

__device__ float g_cs[NBLK][DDIM];   // per-block colsum(source)
__device__ float g_ct[NBLK][DDIM];   // per-block colsum(target)
__device__ float g_sq[NBLK];         // per-block sum of squares (s and t)
__device__ unsigned int g_count;     // zero-init; reset by finalizer each run

__global__ __launch_bounds__(NTHR)
void mmd_fused(const float4* __restrict__ s4, const float4* __restrict__ t4,
               int B, float* __restrict__ out) {
    const int tid = threadIdx.x;
    const int c4  = tid & 63;    // float4 column group (0..63)
    const int ro  = tid >> 6;    // row offset within 8-row tile (0..7)

    // ---------------- Phase 1: streaming partials ----------------
    float4 as = make_float4(0.f, 0.f, 0.f, 0.f);
    float4 at = make_float4(0.f, 0.f, 0.f, 0.f);
    float  sq = 0.f;

    for (int r = blockIdx.x * 8 + ro; r < B; r += NBLK * 8) {
        float4 v = s4[(long)r * D4 + c4];
        as.x += v.x; as.y += v.y; as.z += v.z; as.w += v.w;
        sq += v.x * v.x + v.y * v.y + v.z * v.z + v.w * v.w;
        float4 w = t4[(long)r * D4 + c4];
        at.x += w.x; at.y += w.y; at.z += w.z; at.w += w.w;
        sq += w.x * w.x + w.y * w.y + w.z * w.z + w.w * w.w;
    }

    __shared__ float4 sms[NTHR];
    __shared__ float4 smt[NTHR];
    __shared__ float  smq[NTHR];

    sms[tid] = as; smt[tid] = at; smq[tid] = sq;
    __syncthreads();

    // reduce over the 8 row-offsets (layout: index = ro*64 + c4 = tid)
    #pragma unroll
    for (int half = 4; half >= 1; half >>= 1) {
        if (ro < half) {
            float4 a = sms[tid], b = sms[tid + half * 64];
            a.x += b.x; a.y += b.y; a.z += b.z; a.w += b.w;
            sms[tid] = a;
            float4 c = smt[tid], d = smt[tid + half * 64];
            c.x += d.x; c.y += d.y; c.z += d.z; c.w += d.w;
            smt[tid] = c;
        }
        __syncthreads();
    }
    // sum-of-squares tree
    #pragma unroll
    for (int s = NTHR / 2; s > 0; s >>= 1) {
        if (tid < s) smq[tid] += smq[tid + s];
        __syncthreads();
    }

    if (ro == 0) {
        reinterpret_cast<float4*>(g_cs[blockIdx.x])[c4] = sms[c4];
        reinterpret_cast<float4*>(g_ct[blockIdx.x])[c4] = smt[c4];
    }
    if (tid == 0) g_sq[blockIdx.x] = smq[0];

    // ---------------- handoff: last block finalizes ----------------
    __shared__ unsigned int lastFlag;
    __threadfence();                 // make this block's partials device-visible
    __syncthreads();
    if (tid == 0) {
        unsigned int v = atomicAdd(&g_count, 1u);
        lastFlag = (v == (unsigned int)(gridDim.x - 1));
    }
    __syncthreads();
    if (!lastFlag) return;
    __threadfence();                 // order: counter observed -> partial reads

    // ---------------- Phase 2: finalize (one block) ----------------
    // Thread layout: p = tid>>6 (0..7) handles a slice of the 148 partials
    // for float4 column group c4. 19 blocks per slice -> ~38 independent
    // float4 L2 loads per thread.
    const int p  = tid >> 6;
    const int b0 = p * 19;
    const int b1 = (b0 + 19 < NBLK) ? (b0 + 19) : NBLK;

    float4 cs = make_float4(0.f, 0.f, 0.f, 0.f);
    float4 ct = make_float4(0.f, 0.f, 0.f, 0.f);
    #pragma unroll 4
    for (int b = b0; b < b1; b++) {
        float4 v = reinterpret_cast<const float4*>(g_cs[b])[c4];
        cs.x += v.x; cs.y += v.y; cs.z += v.z; cs.w += v.w;
        float4 w = reinterpret_cast<const float4*>(g_ct[b])[c4];
        ct.x += w.x; ct.y += w.y; ct.z += w.z; ct.w += w.w;
    }

    sms[tid] = cs; smt[tid] = ct;
    __syncthreads();
    #pragma unroll
    for (int half = 4; half >= 1; half >>= 1) {
        if (p < half) {
            float4 a = sms[tid], b = sms[tid + half * 64];
            a.x += b.x; a.y += b.y; a.z += b.z; a.w += b.w;
            sms[tid] = a;
            float4 c = smt[tid], d = smt[tid + half * 64];
            c.x += d.x; c.y += d.y; c.z += d.z; c.w += d.w;
            smt[tid] = c;
        }
        __syncthreads();
    }

    __shared__ double sd[64];    // ||delta||^2 partials
    __shared__ double sm2[64];   // ||msum||^2 partials
    __shared__ double ssq[NTHR]; // sum-of-squares partials

    if (p == 0) {
        float4 a = sms[c4], b = smt[c4];
        double dx = (double)a.x - (double)b.x;
        double dy = (double)a.y - (double)b.y;
        double dz = (double)a.z - (double)b.z;
        double dw = (double)a.w - (double)b.w;
        sd[c4] = dx * dx + dy * dy + dz * dz + dw * dw;
        double mx = (double)a.x + (double)b.x;
        double my = (double)a.y + (double)b.y;
        double mz = (double)a.z + (double)b.z;
        double mw = (double)a.w + (double)b.w;
        sm2[c4] = mx * mx + my * my + mz * mz + mw * mw;
    }
    ssq[tid] = (tid < NBLK) ? (double)g_sq[tid] : 0.0;
    __syncthreads();

    #pragma unroll
    for (int s = NTHR / 2; s > 0; s >>= 1) {
        if (tid < s) ssq[tid] += ssq[tid + s];
        if (s <= 32 && tid < s) {
            sd[tid]  += sd[tid + s];
            sm2[tid] += sm2[tid + s];
        }
        __syncthreads();
    }

    if (tid == 0) {
        double n   = 2.0 * (double)B;
        double Bd  = (double)B;
        double res = 7.75 * n * (n - 1.0) * sd[0]
                   / ((n * ssq[0] - sm2[0]) * Bd * Bd);
        out[0] = (float)res;
        g_count = 0;   // reset for next graph replay (deterministic)
    }
}

extern "C" void kernel_launch(void* const* d_in, const int* in_sizes, int n_in,
                              void* d_out, int out_size) {
    const float* s = (const float*)d_in[0];
    const float* t = (const float*)d_in[1];
    int B = in_sizes[0] / DDIM;   // 4096 here

    mmd_fused<<<NBLK, NTHR>>>((const float4*)s, (const float4*)t, B, (float*)d_out);
}

// round 3
// speedup vs baseline: 1.2416x; 1.2416x over previous
#include <cuda_runtime.h>

// MMD loss in closed form over column statistics:
//   result = 7.75 * n(n-1) * ||Delta||^2 / ((n*S - ||M||^2) * B^2),  n = 2B
// where Delta_c = colsum(s)_c - colsum(t)_c, M_c = colsum(s)_c + colsum(t)_c,
// S = sum(s^2) + sum(t^2). The (max-min) scale factor cancels exactly.
//
// Single kernel: each block streams a slice, reduces to 256 delta / 256 msum
// floats + 1 sq scalar in shared, then RED.ADD.F64 into tiny global
// accumulators. Last-arriving block reads the 4KB of totals and finalizes.

#define NBLK 148
#define NTHR 512
#define DDIM 256
#define D4   64   // DDIM / 4

__device__ double g_delta[DDIM];   // column sums of (s - t), zero-init / reset
__device__ double g_msum[DDIM];    // column sums of (s + t)
__device__ double g_sq;            // total sum of squares
__device__ unsigned int g_count;

__global__ __launch_bounds__(NTHR)
void mmd_fused(const float4* __restrict__ s4, const float4* __restrict__ t4,
               int B, float* __restrict__ out) {
    const int tid = threadIdx.x;
    const int c4  = tid & 63;    // float4 column group (fixed: stride % 64 == 0)
    const int ro  = tid >> 6;    // 0..7

    const long N4     = (long)B * D4;        // float4 elements per array
    const long total  = 2 * N4;              // s followed (virtually) by t
    const long stride = (long)NBLK * NTHR;

    // ---------------- Phase 1: streaming ----------------
    float4 ad = make_float4(0.f, 0.f, 0.f, 0.f);  // signed accum (s - t)
    float4 am = make_float4(0.f, 0.f, 0.f, 0.f);  // unsigned accum (s + t)
    float  sq = 0.f;

    #pragma unroll 4
    for (long e = (long)blockIdx.x * NTHR + tid; e < total; e += stride) {
        const float4* p = (e < N4) ? (s4 + e) : (t4 + (e - N4));
        float sign = (e < N4) ? 1.0f : -1.0f;
        float4 v = *p;
        am.x += v.x; am.y += v.y; am.z += v.z; am.w += v.w;
        ad.x = fmaf(sign, v.x, ad.x);
        ad.y = fmaf(sign, v.y, ad.y);
        ad.z = fmaf(sign, v.z, ad.z);
        ad.w = fmaf(sign, v.w, ad.w);
        sq = fmaf(v.x, v.x, sq);
        sq = fmaf(v.y, v.y, sq);
        sq = fmaf(v.z, v.z, sq);
        sq = fmaf(v.w, v.w, sq);
    }

    __shared__ float4 smd[NTHR];
    __shared__ float4 smm[NTHR];
    __shared__ float  smq[NTHR];

    smd[tid] = ad; smm[tid] = am; smq[tid] = sq;
    __syncthreads();

    // reduce over the 8 row-offset groups (index = ro*64 + c4)
    #pragma unroll
    for (int half = 4; half >= 1; half >>= 1) {
        if (ro < half) {
            float4 a = smd[tid], b = smd[tid + half * 64];
            a.x += b.x; a.y += b.y; a.z += b.z; a.w += b.w;
            smd[tid] = a;
            float4 c = smm[tid], d = smm[tid + half * 64];
            c.x += d.x; c.y += d.y; c.z += d.z; c.w += d.w;
            smm[tid] = c;
        }
        __syncthreads();
    }
    #pragma unroll
    for (int s = NTHR / 2; s > 0; s >>= 1) {
        if (tid < s) smq[tid] += smq[tid + s];
        __syncthreads();
    }

    // fire-and-forget double atomics (RED.ADD.F64) -- tiny contention
    if (tid < DDIM) {
        float d = reinterpret_cast<const float*>(smd)[tid];  // column = tid
        float m = reinterpret_cast<const float*>(smm)[tid];
        atomicAdd(&g_delta[tid], (double)d);
        atomicAdd(&g_msum[tid],  (double)m);
    }
    if (tid == 0) atomicAdd(&g_sq, (double)smq[0]);

    // ---------------- handoff: last block finalizes ----------------
    __shared__ unsigned int lastFlag;
    __threadfence();
    __syncthreads();
    if (tid == 0)
        lastFlag = (atomicAdd(&g_count, 1u) == (unsigned)(NBLK - 1));
    __syncthreads();
    if (!lastFlag) return;
    __threadfence();

    // ---------------- Phase 2: finalize (4KB of reads) ----------------
    __shared__ double rd[NTHR];
    __shared__ double rm[NTHR];
    double sd = 0.0, sm2 = 0.0;
    if (tid < DDIM) {
        double d = g_delta[tid]; sd  = d * d;
        double m = g_msum[tid];  sm2 = m * m;
    }
    rd[tid] = sd; rm[tid] = sm2;
    __syncthreads();
    #pragma unroll
    for (int s = NTHR / 2; s > 0; s >>= 1) {
        if (tid < s) { rd[tid] += rd[tid + s]; rm[tid] += rm[tid + s]; }
        __syncthreads();
    }

    if (tid < DDIM) { g_delta[tid] = 0.0; g_msum[tid] = 0.0; }  // reset for replay
    if (tid == 0) {
        double S  = g_sq;
        double n  = 2.0 * (double)B;
        double Bd = (double)B;
        double res = 7.75 * n * (n - 1.0) * rd[0]
                   / ((n * S - rm[0]) * Bd * Bd);
        out[0] = (float)res;
        g_sq = 0.0;
        g_count = 0u;
    }
}

extern "C" void kernel_launch(void* const* d_in, const int* in_sizes, int n_in,
                              void* d_out, int out_size) {
    const float* s = (const float*)d_in[0];
    const float* t = (const float*)d_in[1];
    int B = in_sizes[0] / DDIM;   // 4096 here

    mmd_fused<<<NBLK, NTHR>>>((const float4*)s, (const float4*)t, B, (float*)d_out);
}

// round 4
// speedup vs baseline: 1.4799x; 1.1920x over previous
#include <cuda_runtime.h>

// MMD loss in closed form over column statistics:
//   result = 7.75 * n(n-1) * ||Delta||^2 / ((n*S - ||M||^2) * B^2),  n = 2B
// Delta_c = colsum(s-t)_c, M_c = colsum(s+t)_c, S = sum(s^2)+sum(t^2).
// The (max-min) scale factor cancels exactly.
//
// One kernel: 128 blocks x 1024 threads. For the 4096x256 shape each thread
// does exactly 2+2 static float4 loads (no loop). Per-block column partials
// go through 4-way-banked f64 atomics; the last block finalizes.

#define NBLK 128
#define NTHR 1024
#define DDIM 256
#define D4   64          // DDIM / 4
#define TOT  (NBLK * NTHR)   // 131072 threads
#define NBANK 4

__device__ double g_delta[NBANK][DDIM];
__device__ double g_msum[NBANK][DDIM];
__device__ double g_sqb[NBANK];
__device__ unsigned int g_count;

__global__ __launch_bounds__(NTHR)
void mmd_fused(const float4* __restrict__ s4, const float4* __restrict__ t4,
               long N4, int B, float* __restrict__ out) {
    const int tid = threadIdx.x;
    const int c4  = tid & 63;    // float4 column group (stride TOT % 64 == 0)
    const int ro  = tid >> 6;    // 0..15

    // ---------------- Phase 1: streaming ----------------
    float4 as, at;
    float  sq;

    if (N4 == (long)TOT * 2) {
        // static fast path: exactly 2 float4 per array per thread
        const long i0 = (long)blockIdx.x * NTHR + tid;
        const long i1 = i0 + TOT;
        float4 a = s4[i0], b = s4[i1];
        float4 c = t4[i0], d = t4[i1];
        as.x = a.x + b.x; as.y = a.y + b.y; as.z = a.z + b.z; as.w = a.w + b.w;
        at.x = c.x + d.x; at.y = c.y + d.y; at.z = c.z + d.z; at.w = c.w + d.w;
        sq = a.x*a.x + a.y*a.y + a.z*a.z + a.w*a.w
           + b.x*b.x + b.y*b.y + b.z*b.z + b.w*b.w
           + c.x*c.x + c.y*c.y + c.z*c.z + c.w*c.w
           + d.x*d.x + d.y*d.y + d.z*d.z + d.w*d.w;
    } else {
        as = make_float4(0.f,0.f,0.f,0.f);
        at = make_float4(0.f,0.f,0.f,0.f);
        sq = 0.f;
        for (long e = (long)blockIdx.x * NTHR + tid; e < N4; e += TOT) {
            float4 v = s4[e];
            as.x += v.x; as.y += v.y; as.z += v.z; as.w += v.w;
            sq += v.x*v.x + v.y*v.y + v.z*v.z + v.w*v.w;
            float4 w = t4[e];
            at.x += w.x; at.y += w.y; at.z += w.z; at.w += w.w;
            sq += w.x*w.x + w.y*w.y + w.z*w.z + w.w*w.w;
        }
    }

    // delta / msum per thread
    float4 ad, am;
    ad.x = as.x - at.x; ad.y = as.y - at.y; ad.z = as.z - at.z; ad.w = as.w - at.w;
    am.x = as.x + at.x; am.y = as.y + at.y; am.z = as.z + at.z; am.w = as.w + at.w;

    // warp-reduce sq via shuffles
    #pragma unroll
    for (int o = 16; o > 0; o >>= 1) sq += __shfl_down_sync(0xffffffffu, sq, o);

    __shared__ float4 smd[NTHR];
    __shared__ float4 smm[NTHR];
    __shared__ float  smq[32];

    smd[tid] = ad; smm[tid] = am;
    if ((tid & 31) == 0) smq[tid >> 5] = sq;
    __syncthreads();

    // column tree over the 16 row-groups (index = ro*64 + c4)
    #pragma unroll
    for (int half = 8; half >= 1; half >>= 1) {
        if (ro < half) {
            float4 a = smd[tid], b = smd[tid + half * 64];
            a.x += b.x; a.y += b.y; a.z += b.z; a.w += b.w;
            smd[tid] = a;
            float4 c = smm[tid], d = smm[tid + half * 64];
            c.x += d.x; c.y += d.y; c.z += d.z; c.w += d.w;
            smm[tid] = c;
        }
        __syncthreads();
    }

    // banked f64 atomics (contention NBLK/NBANK = 32 per address)
    const int bank = blockIdx.x & (NBANK - 1);
    if (tid < DDIM) {
        atomicAdd(&g_delta[bank][tid], (double)reinterpret_cast<const float*>(smd)[tid]);
        atomicAdd(&g_msum[bank][tid],  (double)reinterpret_cast<const float*>(smm)[tid]);
    }
    if (tid == 0) {
        float q = 0.f;
        #pragma unroll
        for (int w = 0; w < 32; w++) q += smq[w];
        atomicAdd(&g_sqb[bank], (double)q);
    }

    // ---------------- handoff ----------------
    __shared__ unsigned int lastFlag;
    __threadfence();
    __syncthreads();
    if (tid == 0)
        lastFlag = (atomicAdd(&g_count, 1u) == (unsigned)(NBLK - 1));
    __syncthreads();
    if (!lastFlag) return;
    __threadfence();

    // ---------------- Phase 2: finalize ----------------
    __shared__ double rd[DDIM];
    __shared__ double rm[DDIM];
    if (tid < DDIM) {
        double d = g_delta[0][tid] + g_delta[1][tid]
                 + g_delta[2][tid] + g_delta[3][tid];
        double m = g_msum[0][tid] + g_msum[1][tid]
                 + g_msum[2][tid] + g_msum[3][tid];
        rd[tid] = d * d;
        rm[tid] = m * m;
        // reset for next replay
        g_delta[0][tid] = 0.0; g_delta[1][tid] = 0.0;
        g_delta[2][tid] = 0.0; g_delta[3][tid] = 0.0;
        g_msum[0][tid] = 0.0;  g_msum[1][tid] = 0.0;
        g_msum[2][tid] = 0.0;  g_msum[3][tid] = 0.0;
    }
    __syncthreads();
    #pragma unroll
    for (int s = DDIM / 2; s > 0; s >>= 1) {
        if (tid < s) { rd[tid] += rd[tid + s]; rm[tid] += rm[tid + s]; }
        __syncthreads();
    }

    if (tid == 0) {
        double S  = g_sqb[0] + g_sqb[1] + g_sqb[2] + g_sqb[3];
        double n  = 2.0 * (double)B;
        double Bd = (double)B;
        double res = 7.75 * n * (n - 1.0) * rd[0]
                   / ((n * S - rm[0]) * Bd * Bd);
        out[0] = (float)res;
        g_sqb[0] = 0.0; g_sqb[1] = 0.0; g_sqb[2] = 0.0; g_sqb[3] = 0.0;
        g_count = 0u;
    }
}

extern "C" void kernel_launch(void* const* d_in, const int* in_sizes, int n_in,
                              void* d_out, int out_size) {
    const float* s = (const float*)d_in[0];
    const float* t = (const float*)d_in[1];
    int B = in_sizes[0] / DDIM;          // 4096 here
    long N4 = (long)B * D4;              // float4 count per array

    mmd_fused<<<NBLK, NTHR>>>((const float4*)s, (const float4*)t, N4, B,
                              (float*)d_out);
}

// round 5
// speedup vs baseline: 1.6370x; 1.1062x over previous
#include <cuda_runtime.h>

// MMD loss in closed form over column statistics:
//   result = 7.75 * n(n-1) * ||Delta||^2 / ((n*S - ||M||^2) * B^2),  n = 2B
// Delta_c = colsum(s-t)_c, M_c = colsum(s+t)_c, S = sum(s^2)+sum(t^2).
// The (max-min) scale factor cancels exactly.
//
// 148 blocks x 512 threads, each thread up to 4+4 predicated float4 loads
// (MLP 8). Single-barrier epilogue, banked f64 atomics, last block finalizes.

#define NBLK 148
#define NTHR 512
#define DDIM 256
#define D4   64                  // DDIM / 4
#define STRIDE ((long)NBLK * NTHR)   // 75776, divisible by 64
#define NBANK 4

__device__ double g_delta[NBANK][DDIM];
__device__ double g_msum[NBANK][DDIM];
__device__ double g_sqb[NBANK];
__device__ unsigned int g_count;

__global__ __launch_bounds__(NTHR)
void mmd_fused(const float4* __restrict__ s4, const float4* __restrict__ t4,
               long N4, int B, float* __restrict__ out) {
    const int tid = threadIdx.x;
    const int c4  = tid & 63;    // float4 column group (STRIDE % 64 == 0)
    const int ro  = tid >> 6;    // 0..7

    // ---------------- Phase 1: streaming, MLP 8 ----------------
    const long  base = (long)blockIdx.x * NTHR + tid;
    const float4 z4  = make_float4(0.f, 0.f, 0.f, 0.f);

    float4 as = z4, at = z4;
    float  sq = 0.f;

    if (N4 <= 4 * STRIDE) {
        // fast path (true for 4096x256): up to 4 strided loads per array,
        // all issued before any use.
        const long e0 = base, e1 = base + STRIDE,
                   e2 = base + 2 * STRIDE, e3 = base + 3 * STRIDE;
        float4 a0 = (e0 < N4) ? s4[e0] : z4;
        float4 a1 = (e1 < N4) ? s4[e1] : z4;
        float4 a2 = (e2 < N4) ? s4[e2] : z4;
        float4 a3 = (e3 < N4) ? s4[e3] : z4;
        float4 b0 = (e0 < N4) ? t4[e0] : z4;
        float4 b1 = (e1 < N4) ? t4[e1] : z4;
        float4 b2 = (e2 < N4) ? t4[e2] : z4;
        float4 b3 = (e3 < N4) ? t4[e3] : z4;

        as.x = (a0.x + a1.x) + (a2.x + a3.x);
        as.y = (a0.y + a1.y) + (a2.y + a3.y);
        as.z = (a0.z + a1.z) + (a2.z + a3.z);
        as.w = (a0.w + a1.w) + (a2.w + a3.w);
        at.x = (b0.x + b1.x) + (b2.x + b3.x);
        at.y = (b0.y + b1.y) + (b2.y + b3.y);
        at.z = (b0.z + b1.z) + (b2.z + b3.z);
        at.w = (b0.w + b1.w) + (b2.w + b3.w);

        sq = a0.x*a0.x + a0.y*a0.y + a0.z*a0.z + a0.w*a0.w
           + a1.x*a1.x + a1.y*a1.y + a1.z*a1.z + a1.w*a1.w
           + a2.x*a2.x + a2.y*a2.y + a2.z*a2.z + a2.w*a2.w
           + a3.x*a3.x + a3.y*a3.y + a3.z*a3.z + a3.w*a3.w
           + b0.x*b0.x + b0.y*b0.y + b0.z*b0.z + b0.w*b0.w
           + b1.x*b1.x + b1.y*b1.y + b1.z*b1.z + b1.w*b1.w
           + b2.x*b2.x + b2.y*b2.y + b2.z*b2.z + b2.w*b2.w
           + b3.x*b3.x + b3.y*b3.y + b3.z*b3.z + b3.w*b3.w;
    } else {
        for (long e = base; e < N4; e += STRIDE) {
            float4 v = s4[e];
            as.x += v.x; as.y += v.y; as.z += v.z; as.w += v.w;
            sq += v.x*v.x + v.y*v.y + v.z*v.z + v.w*v.w;
            float4 w = t4[e];
            at.x += w.x; at.y += w.y; at.z += w.z; at.w += w.w;
            sq += w.x*w.x + w.y*w.y + w.z*w.z + w.w*w.w;
        }
    }

    float4 ad, am;
    ad.x = as.x - at.x; ad.y = as.y - at.y; ad.z = as.z - at.z; ad.w = as.w - at.w;
    am.x = as.x + at.x; am.y = as.y + at.y; am.z = as.z + at.z; am.w = as.w + at.w;

    // warp-reduce sq
    #pragma unroll
    for (int o = 16; o > 0; o >>= 1) sq += __shfl_down_sync(0xffffffffu, sq, o);

    // ---------------- single-barrier epilogue ----------------
    __shared__ float4 smd[8][64];   // [row-group][col-group] of (s - t)
    __shared__ float4 smm[8][64];   // [row-group][col-group] of (s + t)
    __shared__ float  smq[16];

    smd[ro][c4] = ad;
    smm[ro][c4] = am;
    if ((tid & 31) == 0) smq[tid >> 5] = sq;
    __syncthreads();

    const int bank = blockIdx.x & (NBANK - 1);
    if (tid < DDIM) {
        const float* fd = &reinterpret_cast<const float*>(smd)[tid];
        const float* fm = &reinterpret_cast<const float*>(smm)[tid];
        float d = 0.f, m = 0.f;
        #pragma unroll
        for (int g = 0; g < 8; g++) { d += fd[g * DDIM]; m += fm[g * DDIM]; }
        atomicAdd(&g_delta[bank][tid], (double)d);
        atomicAdd(&g_msum[bank][tid],  (double)m);
    } else if (tid == DDIM) {
        float q = 0.f;
        #pragma unroll
        for (int w = 0; w < 16; w++) q += smq[w];
        atomicAdd(&g_sqb[bank], (double)q);
    }

    // ---------------- handoff: last block finalizes ----------------
    __shared__ unsigned int lastFlag;
    __threadfence();
    __syncthreads();
    if (tid == 0)
        lastFlag = (atomicAdd(&g_count, 1u) == (unsigned)(NBLK - 1));
    __syncthreads();
    if (!lastFlag) return;
    __threadfence();

    // ---------------- Phase 2: finalize (16KB of L2 reads) ----------------
    __shared__ double rd[DDIM];
    __shared__ double rm[DDIM];
    if (tid < DDIM) {
        double d = (g_delta[0][tid] + g_delta[1][tid])
                 + (g_delta[2][tid] + g_delta[3][tid]);
        double m = (g_msum[0][tid] + g_msum[1][tid])
                 + (g_msum[2][tid] + g_msum[3][tid]);
        rd[tid] = d * d;
        rm[tid] = m * m;
        g_delta[0][tid] = 0.0; g_delta[1][tid] = 0.0;
        g_delta[2][tid] = 0.0; g_delta[3][tid] = 0.0;
        g_msum[0][tid] = 0.0;  g_msum[1][tid] = 0.0;
        g_msum[2][tid] = 0.0;  g_msum[3][tid] = 0.0;
    }
    __syncthreads();
    #pragma unroll
    for (int s = DDIM / 2; s > 0; s >>= 1) {
        if (tid < s) { rd[tid] += rd[tid + s]; rm[tid] += rm[tid + s]; }
        __syncthreads();
    }

    if (tid == 0) {
        double S  = (g_sqb[0] + g_sqb[1]) + (g_sqb[2] + g_sqb[3]);
        double n  = 2.0 * (double)B;
        double Bd = (double)B;
        double res = 7.75 * n * (n - 1.0) * rd[0]
                   / ((n * S - rm[0]) * Bd * Bd);
        out[0] = (float)res;
        g_sqb[0] = 0.0; g_sqb[1] = 0.0; g_sqb[2] = 0.0; g_sqb[3] = 0.0;
        g_count = 0u;
    }
}

extern "C" void kernel_launch(void* const* d_in, const int* in_sizes, int n_in,
                              void* d_out, int out_size) {
    const float* s = (const float*)d_in[0];
    const float* t = (const float*)d_in[1];
    int B = in_sizes[0] / DDIM;          // 4096 here
    long N4 = (long)B * D4;              // float4 count per array

    mmd_fused<<<NBLK, NTHR>>>((const float4*)s, (const float4*)t, N4, B,
                              (float*)d_out);
}

// round 6
// speedup vs baseline: 1.6426x; 1.0034x over previous
#include <cuda_runtime.h>

// MMD loss in closed form over column statistics:
//   result = 7.75 * n(n-1) * ||Delta||^2 / ((n*S - ||M||^2) * B^2),  n = 2B
// Delta_c = colsum(s-t)_c, M_c = colsum(s+t)_c, S = sum(s^2)+sum(t^2).
// The (max-min) scale factor cancels exactly.
//
// 148 blocks x 512 threads, up to 4+4 predicated float4 loads per thread
// (MLP 8). Single-barrier block epilogue -> 2-way-banked f64 atomics.
// Last block finalizes with warp-shuffle reductions (2 barriers total).

#define NBLK 148
#define NTHR 512
#define DDIM 256
#define D4   64                      // DDIM / 4
#define STRIDE ((long)NBLK * NTHR)   // 75776, divisible by 64
#define NBANK 2

__device__ double g_delta[NBANK][DDIM];
__device__ double g_msum[NBANK][DDIM];
__device__ double g_sqb[NBANK];
__device__ unsigned int g_count;

__global__ __launch_bounds__(NTHR)
void mmd_fused(const float4* __restrict__ s4, const float4* __restrict__ t4,
               long N4, int B, float* __restrict__ out) {
    const int tid = threadIdx.x;
    const int c4  = tid & 63;    // float4 column group (STRIDE % 64 == 0)
    const int ro  = tid >> 6;    // 0..7

    // ---------------- Phase 1: streaming, MLP 8 ----------------
    const long  base = (long)blockIdx.x * NTHR + tid;
    const float4 z4  = make_float4(0.f, 0.f, 0.f, 0.f);

    float4 as = z4, at = z4;
    float  sq = 0.f;

    if (N4 <= 4 * STRIDE) {
        const long e0 = base, e1 = base + STRIDE,
                   e2 = base + 2 * STRIDE, e3 = base + 3 * STRIDE;
        float4 a0 = (e0 < N4) ? s4[e0] : z4;
        float4 a1 = (e1 < N4) ? s4[e1] : z4;
        float4 a2 = (e2 < N4) ? s4[e2] : z4;
        float4 a3 = (e3 < N4) ? s4[e3] : z4;
        float4 b0 = (e0 < N4) ? t4[e0] : z4;
        float4 b1 = (e1 < N4) ? t4[e1] : z4;
        float4 b2 = (e2 < N4) ? t4[e2] : z4;
        float4 b3 = (e3 < N4) ? t4[e3] : z4;

        as.x = (a0.x + a1.x) + (a2.x + a3.x);
        as.y = (a0.y + a1.y) + (a2.y + a3.y);
        as.z = (a0.z + a1.z) + (a2.z + a3.z);
        as.w = (a0.w + a1.w) + (a2.w + a3.w);
        at.x = (b0.x + b1.x) + (b2.x + b3.x);
        at.y = (b0.y + b1.y) + (b2.y + b3.y);
        at.z = (b0.z + b1.z) + (b2.z + b3.z);
        at.w = (b0.w + b1.w) + (b2.w + b3.w);

        sq = a0.x*a0.x + a0.y*a0.y + a0.z*a0.z + a0.w*a0.w
           + a1.x*a1.x + a1.y*a1.y + a1.z*a1.z + a1.w*a1.w
           + a2.x*a2.x + a2.y*a2.y + a2.z*a2.z + a2.w*a2.w
           + a3.x*a3.x + a3.y*a3.y + a3.z*a3.z + a3.w*a3.w
           + b0.x*b0.x + b0.y*b0.y + b0.z*b0.z + b0.w*b0.w
           + b1.x*b1.x + b1.y*b1.y + b1.z*b1.z + b1.w*b1.w
           + b2.x*b2.x + b2.y*b2.y + b2.z*b2.z + b2.w*b2.w
           + b3.x*b3.x + b3.y*b3.y + b3.z*b3.z + b3.w*b3.w;
    } else {
        for (long e = base; e < N4; e += STRIDE) {
            float4 v = s4[e];
            as.x += v.x; as.y += v.y; as.z += v.z; as.w += v.w;
            sq += v.x*v.x + v.y*v.y + v.z*v.z + v.w*v.w;
            float4 w = t4[e];
            at.x += w.x; at.y += w.y; at.z += w.z; at.w += w.w;
            sq += w.x*w.x + w.y*w.y + w.z*w.z + w.w*w.w;
        }
    }

    float4 ad, am;
    ad.x = as.x - at.x; ad.y = as.y - at.y; ad.z = as.z - at.z; ad.w = as.w - at.w;
    am.x = as.x + at.x; am.y = as.y + at.y; am.z = as.z + at.z; am.w = as.w + at.w;

    #pragma unroll
    for (int o = 16; o > 0; o >>= 1) sq += __shfl_down_sync(0xffffffffu, sq, o);

    // ---------------- single-barrier block epilogue ----------------
    __shared__ float4 smd[8][64];
    __shared__ float4 smm[8][64];
    __shared__ float  smq[16];

    smd[ro][c4] = ad;
    smm[ro][c4] = am;
    if ((tid & 31) == 0) smq[tid >> 5] = sq;
    __syncthreads();

    const int bank = blockIdx.x & (NBANK - 1);
    if (tid < DDIM) {
        const float* fd = &reinterpret_cast<const float*>(smd)[tid];
        const float* fm = &reinterpret_cast<const float*>(smm)[tid];
        float d = 0.f, m = 0.f;
        #pragma unroll
        for (int g = 0; g < 8; g++) { d += fd[g * DDIM]; m += fm[g * DDIM]; }
        atomicAdd(&g_delta[bank][tid], (double)d);
        atomicAdd(&g_msum[bank][tid],  (double)m);
    } else if (tid == DDIM) {
        float q = 0.f;
        #pragma unroll
        for (int w = 0; w < 16; w++) q += smq[w];
        atomicAdd(&g_sqb[bank], (double)q);
    }

    // ---------------- handoff: last block finalizes ----------------
    __shared__ unsigned int lastFlag;
    __threadfence();
    __syncthreads();
    if (tid == 0)
        lastFlag = (atomicAdd(&g_count, 1u) == (unsigned)(NBLK - 1));
    __syncthreads();
    if (!lastFlag) return;
    __threadfence();

    // ---------------- Phase 2: finalize, shuffle-based ----------------
    __shared__ double wd[8];   // per-warp ||delta||^2 partials (warps 0..7)
    __shared__ double wm[8];

    double dd = 0.0, mm = 0.0;
    if (tid < DDIM) {
        double d = g_delta[0][tid] + g_delta[1][tid];
        double m = g_msum[0][tid]  + g_msum[1][tid];
        dd = d * d;
        mm = m * m;
        // reset for next replay (fire-and-forget)
        g_delta[0][tid] = 0.0; g_delta[1][tid] = 0.0;
        g_msum[0][tid]  = 0.0; g_msum[1][tid]  = 0.0;
    }
    #pragma unroll
    for (int o = 16; o > 0; o >>= 1) {
        dd += __shfl_down_sync(0xffffffffu, dd, o);
        mm += __shfl_down_sync(0xffffffffu, mm, o);
    }
    if (tid < DDIM && (tid & 31) == 0) {
        wd[tid >> 5] = dd;
        wm[tid >> 5] = mm;
    }
    __syncthreads();

    if (tid < 32) {
        double d2 = (tid < 8) ? wd[tid] : 0.0;
        double m2 = (tid < 8) ? wm[tid] : 0.0;
        #pragma unroll
        for (int o = 4; o > 0; o >>= 1) {
            d2 += __shfl_down_sync(0xffffffffu, d2, o);
            m2 += __shfl_down_sync(0xffffffffu, m2, o);
        }
        if (tid == 0) {
            double S  = g_sqb[0] + g_sqb[1];
            double n  = 2.0 * (double)B;
            double Bd = (double)B;
            double res = 7.75 * n * (n - 1.0) * d2
                       / ((n * S - m2) * Bd * Bd);
            out[0] = (float)res;
            g_sqb[0] = 0.0; g_sqb[1] = 0.0;
            g_count = 0u;
        }
    }
}

extern "C" void kernel_launch(void* const* d_in, const int* in_sizes, int n_in,
                              void* d_out, int out_size) {
    const float* s = (const float*)d_in[0];
    const float* t = (const float*)d_in[1];
    int B = in_sizes[0] / DDIM;          // 4096 here
    long N4 = (long)B * D4;              // float4 count per array

    mmd_fused<<<NBLK, NTHR>>>((const float4*)s, (const float4*)t, N4, B,
                              (float*)d_out);
}

// round 7
// speedup vs baseline: 1.7133x; 1.0430x over previous
#include <cuda_runtime.h>

// MMD loss in closed form over column statistics:
//   result = 7.75 * n(n-1) * ||Delta||^2 / ((n*S - ||M||^2) * B^2),  n = 2B
// Delta_c = colsum(s-t)_c, M_c = colsum(s+t)_c, S = sum(s^2)+sum(t^2).
// The (max-min) scale factor cancels exactly.
//
// 148 blocks x 512 threads, up to 4+4 predicated float4 loads per thread
// (MLP 8). Single-barrier block epilogue -> 2-way-banked f64 atomics.
// Handoff via one acq_rel atomic (no threadfence). Last block finalizes
// with warp shuffles while a spare warp prefetches the sq accumulators.

#define NBLK 148
#define NTHR 512
#define DDIM 256
#define D4   64                      // DDIM / 4
#define STRIDE ((long)NBLK * NTHR)   // 75776, divisible by 64
#define NBANK 2

__device__ double g_delta[NBANK][DDIM];
__device__ double g_msum[NBANK][DDIM];
__device__ double g_sqb[NBANK];
__device__ unsigned int g_count;

__global__ __launch_bounds__(NTHR)
void mmd_fused(const float4* __restrict__ s4, const float4* __restrict__ t4,
               long N4, int B, float* __restrict__ out) {
    const int tid = threadIdx.x;
    const int c4  = tid & 63;    // float4 column group (STRIDE % 64 == 0)
    const int ro  = tid >> 6;    // 0..7

    // ---------------- Phase 1: streaming, MLP 8 ----------------
    const long  base = (long)blockIdx.x * NTHR + tid;
    const float4 z4  = make_float4(0.f, 0.f, 0.f, 0.f);

    float4 as = z4, at = z4;
    float  sq = 0.f;

    if (N4 <= 4 * STRIDE) {
        const long e0 = base, e1 = base + STRIDE,
                   e2 = base + 2 * STRIDE, e3 = base + 3 * STRIDE;
        float4 a0 = (e0 < N4) ? s4[e0] : z4;
        float4 a1 = (e1 < N4) ? s4[e1] : z4;
        float4 a2 = (e2 < N4) ? s4[e2] : z4;
        float4 a3 = (e3 < N4) ? s4[e3] : z4;
        float4 b0 = (e0 < N4) ? t4[e0] : z4;
        float4 b1 = (e1 < N4) ? t4[e1] : z4;
        float4 b2 = (e2 < N4) ? t4[e2] : z4;
        float4 b3 = (e3 < N4) ? t4[e3] : z4;

        as.x = (a0.x + a1.x) + (a2.x + a3.x);
        as.y = (a0.y + a1.y) + (a2.y + a3.y);
        as.z = (a0.z + a1.z) + (a2.z + a3.z);
        as.w = (a0.w + a1.w) + (a2.w + a3.w);
        at.x = (b0.x + b1.x) + (b2.x + b3.x);
        at.y = (b0.y + b1.y) + (b2.y + b3.y);
        at.z = (b0.z + b1.z) + (b2.z + b3.z);
        at.w = (b0.w + b1.w) + (b2.w + b3.w);

        sq = a0.x*a0.x + a0.y*a0.y + a0.z*a0.z + a0.w*a0.w
           + a1.x*a1.x + a1.y*a1.y + a1.z*a1.z + a1.w*a1.w
           + a2.x*a2.x + a2.y*a2.y + a2.z*a2.z + a2.w*a2.w
           + a3.x*a3.x + a3.y*a3.y + a3.z*a3.z + a3.w*a3.w
           + b0.x*b0.x + b0.y*b0.y + b0.z*b0.z + b0.w*b0.w
           + b1.x*b1.x + b1.y*b1.y + b1.z*b1.z + b1.w*b1.w
           + b2.x*b2.x + b2.y*b2.y + b2.z*b2.z + b2.w*b2.w
           + b3.x*b3.x + b3.y*b3.y + b3.z*b3.z + b3.w*b3.w;
    } else {
        for (long e = base; e < N4; e += STRIDE) {
            float4 v = s4[e];
            as.x += v.x; as.y += v.y; as.z += v.z; as.w += v.w;
            sq += v.x*v.x + v.y*v.y + v.z*v.z + v.w*v.w;
            float4 w = t4[e];
            at.x += w.x; at.y += w.y; at.z += w.z; at.w += w.w;
            sq += w.x*w.x + w.y*w.y + w.z*w.z + w.w*w.w;
        }
    }

    float4 ad, am;
    ad.x = as.x - at.x; ad.y = as.y - at.y; ad.z = as.z - at.z; ad.w = as.w - at.w;
    am.x = as.x + at.x; am.y = as.y + at.y; am.z = as.z + at.z; am.w = as.w + at.w;

    // ---------------- single-barrier block epilogue ----------------
    __shared__ float4 smd[8][64];
    __shared__ float4 smm[8][64];
    __shared__ float  smq[16];

    // STS first so the barrier-critical path doesn't wait on the shuffles
    smd[ro][c4] = ad;
    smm[ro][c4] = am;

    #pragma unroll
    for (int o = 16; o > 0; o >>= 1) sq += __shfl_down_sync(0xffffffffu, sq, o);
    if ((tid & 31) == 0) smq[tid >> 5] = sq;
    __syncthreads();

    const int bank = blockIdx.x & (NBANK - 1);
    if (tid < DDIM) {
        const float* fd = &reinterpret_cast<const float*>(smd)[tid];
        const float* fm = &reinterpret_cast<const float*>(smm)[tid];
        float d = 0.f, m = 0.f;
        #pragma unroll
        for (int g = 0; g < 8; g++) { d += fd[g * DDIM]; m += fm[g * DDIM]; }
        atomicAdd(&g_delta[bank][tid], (double)d);
        atomicAdd(&g_msum[bank][tid],  (double)m);
    } else if (tid == DDIM) {
        float q = 0.f;
        #pragma unroll
        for (int w = 0; w < 16; w++) q += smq[w];
        atomicAdd(&g_sqb[bank], (double)q);
    }

    // ---------------- handoff: acq_rel counter, no threadfence ----------
    __shared__ unsigned int lastFlag;
    __shared__ double sS;
    __syncthreads();   // all REDs issued; creates happens-before for release
    if (tid == 0) {
        unsigned int v;
        asm volatile("atom.add.acq_rel.gpu.u32 %0, [%1], 1;"
                     : "=r"(v) : "l"(&g_count) : "memory");
        lastFlag = (v == (unsigned)(NBLK - 1));
    }
    __syncthreads();
    if (!lastFlag) return;

    // ---------------- Phase 2: finalize (last block only) ----------------
    __shared__ double wd[8];
    __shared__ double wm[8];

    // spare warp prefetches S while warps 0..7 reduce delta/msum
    if (tid == DDIM) {
        sS = g_sqb[0] + g_sqb[1];
        g_sqb[0] = 0.0; g_sqb[1] = 0.0;
    }

    double dd = 0.0, mm = 0.0;
    if (tid < DDIM) {
        double d = g_delta[0][tid] + g_delta[1][tid];
        double m = g_msum[0][tid]  + g_msum[1][tid];
        dd = d * d;
        mm = m * m;
        g_delta[0][tid] = 0.0; g_delta[1][tid] = 0.0;
        g_msum[0][tid]  = 0.0; g_msum[1][tid]  = 0.0;
    }
    #pragma unroll
    for (int o = 16; o > 0; o >>= 1) {
        dd += __shfl_down_sync(0xffffffffu, dd, o);
        mm += __shfl_down_sync(0xffffffffu, mm, o);
    }
    if (tid < DDIM && (tid & 31) == 0) {
        wd[tid >> 5] = dd;
        wm[tid >> 5] = mm;
    }
    __syncthreads();

    if (tid < 32) {
        double d2 = (tid < 8) ? wd[tid] : 0.0;
        double m2 = (tid < 8) ? wm[tid] : 0.0;
        #pragma unroll
        for (int o = 4; o > 0; o >>= 1) {
            d2 += __shfl_down_sync(0xffffffffu, d2, o);
            m2 += __shfl_down_sync(0xffffffffu, m2, o);
        }
        if (tid == 0) {
            double n  = 2.0 * (double)B;
            double Bd = (double)B;
            double res = 7.75 * n * (n - 1.0) * d2
                       / ((n * sS - m2) * Bd * Bd);
            out[0] = (float)res;
            g_count = 0u;
        }
    }
}

extern "C" void kernel_launch(void* const* d_in, const int* in_sizes, int n_in,
                              void* d_out, int out_size) {
    const float* s = (const float*)d_in[0];
    const float* t = (const float*)d_in[1];
    int B = in_sizes[0] / DDIM;          // 4096 here
    long N4 = (long)B * D4;              // float4 count per array

    mmd_fused<<<NBLK, NTHR>>>((const float4*)s, (const float4*)t, N4, B,
                              (float*)d_out);
}

// round 9
// speedup vs baseline: 1.8599x; 1.0856x over previous
#include <cuda_runtime.h>

// MMD loss in closed form over column statistics:
//   result = 7.75 * n(n-1) * ||Delta||^2 / ((n*S - ||M||^2) * B^2),  n = 2B
// Delta_c = colsum(s-t)_c, M_c = colsum(s+t)_c, S = sum(s^2)+sum(t^2).
// The (max-min) scale factor cancels exactly.
//
// 296 blocks x 512 threads (2 CTAs/SM, one wave): each thread does 2+2
// predicated float4 loads. Single-barrier block epilogue -> 4-way-banked
// f64 atomics. Handoff via one acq_rel atomic. Last block finalizes with
// warp shuffles while a spare warp prefetches the sq accumulators.

#define NBLK 296
#define NTHR 512
#define DDIM 256
#define D4   64                      // DDIM / 4
#define STRIDE ((long)NBLK * NTHR)   // 151552, divisible by 64
#define NBANK 4

__device__ double g_delta[NBANK][DDIM];
__device__ double g_msum[NBANK][DDIM];
__device__ double g_sqb[NBANK];
__device__ unsigned int g_count;

__global__ __launch_bounds__(NTHR)
void mmd_fused(const float4* __restrict__ s4, const float4* __restrict__ t4,
               long N4, int B, float* __restrict__ out) {
    const int tid = threadIdx.x;
    const int c4  = tid & 63;    // float4 column group (STRIDE % 64 == 0)
    const int ro  = tid >> 6;    // 0..7

    // ---------------- Phase 1: streaming (2+2 loads) ----------------
    const long  base = (long)blockIdx.x * NTHR + tid;
    const float4 z4  = make_float4(0.f, 0.f, 0.f, 0.f);

    float4 as = z4, at = z4;
    float  sq = 0.f;

    if (N4 <= 2 * STRIDE) {
        const long e0 = base, e1 = base + STRIDE;
        float4 a0 = (e0 < N4) ? s4[e0] : z4;
        float4 a1 = (e1 < N4) ? s4[e1] : z4;
        float4 b0 = (e0 < N4) ? t4[e0] : z4;
        float4 b1 = (e1 < N4) ? t4[e1] : z4;

        as.x = a0.x + a1.x; as.y = a0.y + a1.y;
        as.z = a0.z + a1.z; as.w = a0.w + a1.w;
        at.x = b0.x + b1.x; at.y = b0.y + b1.y;
        at.z = b0.z + b1.z; at.w = b0.w + b1.w;

        sq = a0.x*a0.x + a0.y*a0.y + a0.z*a0.z + a0.w*a0.w
           + a1.x*a1.x + a1.y*a1.y + a1.z*a1.z + a1.w*a1.w
           + b0.x*b0.x + b0.y*b0.y + b0.z*b0.z + b0.w*b0.w
           + b1.x*b1.x + b1.y*b1.y + b1.z*b1.z + b1.w*b1.w;
    } else {
        for (long e = base; e < N4; e += STRIDE) {
            float4 v = s4[e];
            as.x += v.x; as.y += v.y; as.z += v.z; as.w += v.w;
            sq += v.x*v.x + v.y*v.y + v.z*v.z + v.w*v.w;
            float4 w = t4[e];
            at.x += w.x; at.y += w.y; at.z += w.z; at.w += w.w;
            sq += w.x*w.x + w.y*w.y + w.z*w.z + w.w*w.w;
        }
    }

    float4 ad, am;
    ad.x = as.x - at.x; ad.y = as.y - at.y; ad.z = as.z - at.z; ad.w = as.w - at.w;
    am.x = as.x + at.x; am.y = as.y + at.y; am.z = as.z + at.z; am.w = as.w + at.w;

    // ---------------- single-barrier block epilogue ----------------
    __shared__ float4 smd[8][64];
    __shared__ float4 smm[8][64];
    __shared__ float  smq[16];

    // STS first so the barrier-critical path doesn't wait on the shuffles
    smd[ro][c4] = ad;
    smm[ro][c4] = am;

    #pragma unroll
    for (int o = 16; o > 0; o >>= 1) sq += __shfl_down_sync(0xffffffffu, sq, o);
    if ((tid & 31) == 0) smq[tid >> 5] = sq;
    __syncthreads();

    const int bank = blockIdx.x & (NBANK - 1);
    if (tid < DDIM) {
        const float* fd = &reinterpret_cast<const float*>(smd)[tid];
        const float* fm = &reinterpret_cast<const float*>(smm)[tid];
        float d = 0.f, m = 0.f;
        #pragma unroll
        for (int g = 0; g < 8; g++) { d += fd[g * DDIM]; m += fm[g * DDIM]; }
        atomicAdd(&g_delta[bank][tid], (double)d);
        atomicAdd(&g_msum[bank][tid],  (double)m);
    } else if (tid == DDIM) {
        float q = 0.f;
        #pragma unroll
        for (int w = 0; w < 16; w++) q += smq[w];
        atomicAdd(&g_sqb[bank], (double)q);
    }

    // ---------------- handoff: acq_rel counter, no threadfence ----------
    __shared__ unsigned int lastFlag;
    __shared__ double sS;
    __syncthreads();   // all REDs issued; creates happens-before for release
    if (tid == 0) {
        unsigned int v;
        asm volatile("atom.add.acq_rel.gpu.u32 %0, [%1], 1;"
                     : "=r"(v) : "l"(&g_count) : "memory");
        lastFlag = (v == (unsigned)(NBLK - 1));
    }
    __syncthreads();
    if (!lastFlag) return;

    // ---------------- Phase 2: finalize (last block only) ----------------
    __shared__ double wd[8];
    __shared__ double wm[8];

    // spare warp fetches S while warps 0..7 reduce delta/msum
    if (tid == DDIM) {
        sS = (g_sqb[0] + g_sqb[1]) + (g_sqb[2] + g_sqb[3]);
        g_sqb[0] = 0.0; g_sqb[1] = 0.0; g_sqb[2] = 0.0; g_sqb[3] = 0.0;
    }

    double dd = 0.0, mm = 0.0;
    if (tid < DDIM) {
        double d = (g_delta[0][tid] + g_delta[1][tid])
                 + (g_delta[2][tid] + g_delta[3][tid]);
        double m = (g_msum[0][tid] + g_msum[1][tid])
                 + (g_msum[2][tid] + g_msum[3][tid]);
        dd = d * d;
        mm = m * m;
        g_delta[0][tid] = 0.0; g_delta[1][tid] = 0.0;
        g_delta[2][tid] = 0.0; g_delta[3][tid] = 0.0;
        g_msum[0][tid] = 0.0;  g_msum[1][tid] = 0.0;
        g_msum[2][tid] = 0.0;  g_msum[3][tid] = 0.0;
    }
    #pragma unroll
    for (int o = 16; o > 0; o >>= 1) {
        dd += __shfl_down_sync(0xffffffffu, dd, o);
        mm += __shfl_down_sync(0xffffffffu, mm, o);
    }
    if (tid < DDIM && (tid & 31) == 0) {
        wd[tid >> 5] = dd;
        wm[tid >> 5] = mm;
    }
    __syncthreads();

    if (tid < 32) {
        double d2 = (tid < 8) ? wd[tid] : 0.0;
        double m2 = (tid < 8) ? wm[tid] : 0.0;
        #pragma unroll
        for (int o = 4; o > 0; o >>= 1) {
            d2 += __shfl_down_sync(0xffffffffu, d2, o);
            m2 += __shfl_down_sync(0xffffffffu, m2, o);
        }
        if (tid == 0) {
            double n  = 2.0 * (double)B;
            double Bd = (double)B;
            double res = 7.75 * n * (n - 1.0) * d2
                       / ((n * sS - m2) * Bd * Bd);
            out[0] = (float)res;
            g_count = 0u;
        }
    }
}

extern "C" void kernel_launch(void* const* d_in, const int* in_sizes, int n_in,
                              void* d_out, int out_size) {
    const float* s = (const float*)d_in[0];
    const float* t = (const float*)d_in[1];
    int B = in_sizes[0] / DDIM;          // 4096 here
    long N4 = (long)B * D4;              // float4 count per array

    mmd_fused<<<NBLK, NTHR>>>((const float4*)s, (const float4*)t, N4, B,
                              (float*)d_out);
}